// round 5
// baseline (speedup 1.0000x reference)
#include <cuda_runtime.h>
#include <math.h>

#define B_  4
#define S_  1024
#define D_  768
#define H_  24
#define DH_ 64
#define BS_ (B_*S_)    // 4096 tokens
#define HD_ (H_*DH_)   // 1536

// ---------------- scratch (static device globals; no allocation) ----------------
__device__ float g_q[BS_*HD_];
__device__ float g_k[BS_*HD_];
__device__ float g_v[BS_*HD_];
__device__ float g_z[BS_*HD_];
__device__ float g_qg[BS_*H_];
__device__ float g_kg[BS_*H_];
__device__ float g_wvn[H_*D_*DH_];
__device__ float g_won[H_*DH_*D_];
__device__ float g_invv[HD_];
__device__ float g_invo[HD_];

// ---------------- weight normalization ----------------
// W_V: [H, D, DH], norm over D (stride DH per step). one block per (h,dh)
__global__ void norm_v_kernel(const float* __restrict__ wv, float* __restrict__ invn) {
    int c = blockIdx.x;            // h*64+dh
    int h = c >> 6, dh = c & 63;
    const float* p = wv + (size_t)h * D_ * DH_ + dh;
    float s = 0.f;
    for (int m = threadIdx.x; m < D_; m += 256) { float t = p[(size_t)m * DH_]; s += t * t; }
    __shared__ float red[256];
    red[threadIdx.x] = s; __syncthreads();
    for (int o = 128; o; o >>= 1) { if (threadIdx.x < o) red[threadIdx.x] += red[threadIdx.x + o]; __syncthreads(); }
    if (threadIdx.x == 0) invn[c] = 1.0f / fmaxf(sqrtf(red[0]), 1e-12f);
}
// W_O: [H, DH, D], norm over D (contiguous). one block per (h,dh)
__global__ void norm_o_kernel(const float* __restrict__ wo, float* __restrict__ invn) {
    int r = blockIdx.x;
    const float* p = wo + (size_t)r * D_;
    float s = 0.f;
    for (int m = threadIdx.x; m < D_; m += 256) { float t = p[m]; s += t * t; }
    __shared__ float red[256];
    red[threadIdx.x] = s; __syncthreads();
    for (int o = 128; o; o >>= 1) { if (threadIdx.x < o) red[threadIdx.x] += red[threadIdx.x + o]; __syncthreads(); }
    if (threadIdx.x == 0) invn[r] = 1.0f / fmaxf(sqrtf(red[0]), 1e-12f);
}
__global__ void scale_v_kernel(const float* __restrict__ wv, const float* __restrict__ invn,
                               float* __restrict__ out) {
    int i = blockIdx.x * 256 + threadIdx.x;
    int h = i / (D_ * DH_), dh = i & 63;
    out[i] = wv[i] * invn[h * 64 + dh];
}
__global__ void scale_o_kernel(const float* __restrict__ wo, const float* __restrict__ invn,
                               float* __restrict__ out) {
    int i = blockIdx.x * 256 + threadIdx.x;
    out[i] = wo[i] * invn[i / D_];
}

// ---------------- SGEMM: Y[M,N] = A[M,K] @ W + bias ----------------
// BM=128, BN=64, BK=16, 256 threads, 8x4 micro-tile.
// HEADW: W is [H][K][64] per-head (BN=64 == one head, n0 64-aligned)
template<bool HEADW, bool BIAS>
__global__ void sgemm_kernel(const float* __restrict__ A, const float* __restrict__ W,
                             const float* __restrict__ bias, float* __restrict__ Y,
                             int M, int N, int K)
{
    __shared__ __align__(16) float As[16][128];
    __shared__ __align__(16) float Bs[16][64];
    int tid = threadIdx.x;
    int ty = tid >> 4, tx = tid & 15;
    int m0 = blockIdx.y * 128, n0 = blockIdx.x * 64;
    const float* Wb = HEADW ? (W + (size_t)(n0 >> 6) * K * 64) : (W + n0);

    float acc[8][4];
#pragma unroll
    for (int i = 0; i < 8; i++)
#pragma unroll
        for (int j = 0; j < 4; j++) acc[i][j] = 0.f;

    int ai = tid >> 1;           // A row in tile 0..127
    int ak = (tid & 1) * 8;      // k offset 0 or 8
    int bkk = tid >> 4;          // 0..15
    int bn  = (tid & 15) * 4;    // 0..60

    for (int k0 = 0; k0 < K; k0 += 16) {
        const float* pa = A + (size_t)(m0 + ai) * K + k0 + ak;
        float4 a0 = *(const float4*)pa;
        float4 a1 = *(const float4*)(pa + 4);
        As[ak + 0][ai] = a0.x; As[ak + 1][ai] = a0.y; As[ak + 2][ai] = a0.z; As[ak + 3][ai] = a0.w;
        As[ak + 4][ai] = a1.x; As[ak + 5][ai] = a1.y; As[ak + 6][ai] = a1.z; As[ak + 7][ai] = a1.w;
        float4 b4;
        if (HEADW) b4 = *(const float4*)&Wb[(size_t)(k0 + bkk) * 64 + bn];
        else       b4 = *(const float4*)&Wb[(size_t)(k0 + bkk) * N + bn];
        *(float4*)&Bs[bkk][bn] = b4;
        __syncthreads();
#pragma unroll
        for (int kk = 0; kk < 16; kk++) {
            float4 x0 = *(const float4*)&As[kk][ty * 8];
            float4 x1 = *(const float4*)&As[kk][ty * 8 + 4];
            float4 bb = *(const float4*)&Bs[kk][tx * 4];
            float av[8] = {x0.x, x0.y, x0.z, x0.w, x1.x, x1.y, x1.z, x1.w};
            float bv[4] = {bb.x, bb.y, bb.z, bb.w};
#pragma unroll
            for (int i = 0; i < 8; i++)
#pragma unroll
                for (int j = 0; j < 4; j++) acc[i][j] += av[i] * bv[j];
        }
        __syncthreads();
    }
    float4 bb = make_float4(0.f, 0.f, 0.f, 0.f);
    if (BIAS) bb = *(const float4*)&bias[n0 + tx * 4];
#pragma unroll
    for (int i = 0; i < 8; i++) {
        int row = m0 + ty * 8 + i;
        float4 o;
        o.x = acc[i][0] + bb.x; o.y = acc[i][1] + bb.y;
        o.z = acc[i][2] + bb.z; o.w = acc[i][3] + bb.w;
        *(float4*)&Y[(size_t)row * N + n0 + tx * 4] = o;
    }
}

// ---------------- gate projections (DG=1) ----------------
// one block per token; 8 warps x 3 heads each; computes qg and kg dots.
__global__ void gates_kernel(const float* __restrict__ x,
                             const float* __restrict__ wq, const float* __restrict__ wk,
                             const float* __restrict__ bq, const float* __restrict__ bk,
                             float* __restrict__ qg, float* __restrict__ kg)
{
    __shared__ float xs[D_];
    int t = blockIdx.x;
    const float* xp = x + (size_t)t * D_;
    for (int i = threadIdx.x; i < D_; i += 256) xs[i] = xp[i];
    __syncthreads();
    int w = threadIdx.x >> 5, lane = threadIdx.x & 31;
#pragma unroll
    for (int hh = 0; hh < 3; hh++) {
        int h = w * 3 + hh;
        const float* wqp = wq + (size_t)h * D_;
        const float* wkp = wk + (size_t)h * D_;
        float sq = 0.f, sk = 0.f;
        for (int m = lane; m < D_; m += 32) { float xv = xs[m]; sq += xv * wqp[m]; sk += xv * wkp[m]; }
#pragma unroll
        for (int o = 16; o; o >>= 1) {
            sq += __shfl_xor_sync(0xffffffffu, sq, o);
            sk += __shfl_xor_sync(0xffffffffu, sk, o);
        }
        if (lane == 0) {
            qg[(size_t)t * H_ + h] = sq + bq[h];
            kg[(size_t)t * H_ + h] = sk + bk[h];
        }
    }
}

// ---------------- flash-style gated causal attention ----------------
// grid: (B*H, S/64). block 256 = 16x16, 4x4 micro-tile over 64x64.
// online softmax; gate = clip(qg*kg,0,1) applied post-exp (does NOT enter denominator).
__global__ void attn_kernel(const float* __restrict__ q, const float* __restrict__ k,
                            const float* __restrict__ v, const float* __restrict__ qg,
                            const float* __restrict__ kg, float* __restrict__ z)
{
    extern __shared__ float sm[];
    float* Qs  = sm;               // [64][65]
    float* Ks  = Qs + 64 * 65;     // [64][65]
    float* Vs  = Ks + 64 * 65;     // [64][64]
    float* Ps  = Vs + 64 * 64;     // [64][65]
    float* qgs = Ps + 64 * 65;     // [64]
    float* kgs = qgs + 64;         // [64]

    int bh = blockIdx.x; int b = bh / H_, h = bh % H_;
    int qt = blockIdx.y;
    int tid = threadIdx.x, ty = tid >> 4, tx = tid & 15;

    const size_t qbase = ((size_t)(b * S_ + qt * 64) * H_ + h) * 64;

#pragma unroll
    for (int it = 0; it < 4; it++) {
        int id = tid * 4 + it * 1024;
        int r = id >> 6, dh = id & 63;
        float4 t4 = *(const float4*)&q[qbase + (size_t)r * HD_ + dh];
        Qs[r * 65 + dh] = t4.x; Qs[r * 65 + dh + 1] = t4.y;
        Qs[r * 65 + dh + 2] = t4.z; Qs[r * 65 + dh + 3] = t4.w;
    }
    if (tid < 64) qgs[tid] = qg[(size_t)(b * S_ + qt * 64 + tid) * H_ + h];

    float m_r[4], l_r[4], acc[4][4];
#pragma unroll
    for (int i = 0; i < 4; i++) {
        m_r[i] = -1e30f; l_r[i] = 0.f;
#pragma unroll
        for (int j = 0; j < 4; j++) acc[i][j] = 0.f;
    }

    for (int kt = 0; kt <= qt; kt++) {
        __syncthreads();   // protect K/V/P smem from previous iteration readers
        const size_t kbase = ((size_t)(b * S_ + kt * 64) * H_ + h) * 64;
#pragma unroll
        for (int it = 0; it < 4; it++) {
            int id = tid * 4 + it * 1024;
            int r = id >> 6, dh = id & 63;
            float4 t4 = *(const float4*)&k[kbase + (size_t)r * HD_ + dh];
            Ks[r * 65 + dh] = t4.x; Ks[r * 65 + dh + 1] = t4.y;
            Ks[r * 65 + dh + 2] = t4.z; Ks[r * 65 + dh + 3] = t4.w;
            float4 v4 = *(const float4*)&v[kbase + (size_t)r * HD_ + dh];
            *(float4*)&Vs[r * 64 + dh] = v4;
        }
        if (tid < 64) kgs[tid] = kg[(size_t)(b * S_ + kt * 64 + tid) * H_ + h];
        __syncthreads();

        // scores S = Q @ K^T (64x64 tile)
        float s[4][4];
#pragma unroll
        for (int i = 0; i < 4; i++)
#pragma unroll
            for (int j = 0; j < 4; j++) s[i][j] = 0.f;
        for (int dh = 0; dh < 64; dh++) {
            float qv[4], kv[4];
#pragma unroll
            for (int i = 0; i < 4; i++) qv[i] = Qs[(4 * ty + i) * 65 + dh];
#pragma unroll
            for (int j = 0; j < 4; j++) kv[j] = Ks[(4 * tx + j) * 65 + dh];
#pragma unroll
            for (int i = 0; i < 4; i++)
#pragma unroll
                for (int j = 0; j < 4; j++) s[i][j] += qv[i] * kv[j];
        }
#pragma unroll
        for (int i = 0; i < 4; i++)
#pragma unroll
            for (int j = 0; j < 4; j++) s[i][j] *= 0.125f;   // 1/sqrt(64)
        if (kt == qt) {
#pragma unroll
            for (int i = 0; i < 4; i++)
#pragma unroll
                for (int j = 0; j < 4; j++)
                    if (4 * tx + j > 4 * ty + i) s[i][j] = -1e30f;
        }
        // online softmax update + gated P write
#pragma unroll
        for (int i = 0; i < 4; i++) {
            float mm = fmaxf(fmaxf(s[i][0], s[i][1]), fmaxf(s[i][2], s[i][3]));
#pragma unroll
            for (int o = 8; o; o >>= 1) mm = fmaxf(mm, __shfl_xor_sync(0xffffffffu, mm, o));
            float mn = fmaxf(m_r[i], mm);
            float alpha = expf(m_r[i] - mn);
            m_r[i] = mn;
            float p[4], rs = 0.f;
#pragma unroll
            for (int j = 0; j < 4; j++) { p[j] = expf(s[i][j] - mn); rs += p[j]; }
#pragma unroll
            for (int o = 8; o; o >>= 1) rs += __shfl_xor_sync(0xffffffffu, rs, o);
            l_r[i] = l_r[i] * alpha + rs;
#pragma unroll
            for (int j = 0; j < 4; j++) acc[i][j] *= alpha;
            float gq = qgs[4 * ty + i];
#pragma unroll
            for (int j = 0; j < 4; j++) {
                float g = gq * kgs[4 * tx + j];
                g = fminf(fmaxf(g, 0.f), 1.f);
                Ps[(4 * ty + i) * 65 + 4 * tx + j] = g * p[j];
            }
        }
        __syncthreads();
        // O += P_gated @ V
        for (int kk = 0; kk < 64; kk++) {
            float4 v4 = *(const float4*)&Vs[kk * 64 + 4 * tx];
            float vv[4] = {v4.x, v4.y, v4.z, v4.w};
            float pv[4];
#pragma unroll
            for (int i = 0; i < 4; i++) pv[i] = Ps[(4 * ty + i) * 65 + kk];
#pragma unroll
            for (int i = 0; i < 4; i++)
#pragma unroll
                for (int j = 0; j < 4; j++) acc[i][j] += pv[i] * vv[j];
        }
    }

#pragma unroll
    for (int i = 0; i < 4; i++) {
        float inv = 1.f / l_r[i];
        float4 o;
        o.x = acc[i][0] * inv; o.y = acc[i][1] * inv;
        o.z = acc[i][2] * inv; o.w = acc[i][3] * inv;
        *(float4*)&z[qbase + (size_t)(4 * ty + i) * HD_ + 4 * tx] = o;
    }
}

// ---------------- launch ----------------
extern "C" void kernel_launch(void* const* d_in, const int* in_sizes, int n_in,
                              void* d_out, int out_size) {
    const float* x    = (const float*)d_in[0];
    const float* W_Q  = (const float*)d_in[1];
    const float* W_K  = (const float*)d_in[2];
    const float* W_V  = (const float*)d_in[3];
    const float* W_O  = (const float*)d_in[4];
    const float* b_Q  = (const float*)d_in[5];
    const float* b_K  = (const float*)d_in[6];
    const float* b_V  = (const float*)d_in[7];
    const float* WgQ  = (const float*)d_in[8];
    const float* WgK  = (const float*)d_in[9];
    const float* bgQ  = (const float*)d_in[10];
    const float* bgK  = (const float*)d_in[11];
    float* out = (float*)d_out;

    float *p_q, *p_k, *p_v, *p_z, *p_qg, *p_kg, *p_wvn, *p_won, *p_invv, *p_invo;
    cudaGetSymbolAddress((void**)&p_q,    g_q);
    cudaGetSymbolAddress((void**)&p_k,    g_k);
    cudaGetSymbolAddress((void**)&p_v,    g_v);
    cudaGetSymbolAddress((void**)&p_z,    g_z);
    cudaGetSymbolAddress((void**)&p_qg,   g_qg);
    cudaGetSymbolAddress((void**)&p_kg,   g_kg);
    cudaGetSymbolAddress((void**)&p_wvn,  g_wvn);
    cudaGetSymbolAddress((void**)&p_won,  g_won);
    cudaGetSymbolAddress((void**)&p_invv, g_invv);
    cudaGetSymbolAddress((void**)&p_invo, g_invo);

    // 1) weight norms + rescale
    norm_v_kernel<<<HD_, 256>>>(W_V, p_invv);
    norm_o_kernel<<<HD_, 256>>>(W_O, p_invo);
    scale_v_kernel<<<(H_*D_*DH_) / 256, 256>>>(W_V, p_invv, p_wvn);
    scale_o_kernel<<<(H_*DH_*D_) / 256, 256>>>(W_O, p_invo, p_won);

    // 2) Q/K/V projections: [4096,768] @ per-head [768,64] -> [4096,1536] ([B,S,H,DH])
    dim3 pg(HD_ / 64, BS_ / 128);
    sgemm_kernel<true, true><<<pg, 256>>>(x, W_Q,   b_Q, p_q, BS_, HD_, D_);
    sgemm_kernel<true, true><<<pg, 256>>>(x, W_K,   b_K, p_k, BS_, HD_, D_);
    sgemm_kernel<true, true><<<pg, 256>>>(x, p_wvn, b_V, p_v, BS_, HD_, D_);

    // 3) gate projections
    gates_kernel<<<BS_, 256>>>(x, WgQ, WgK, bgQ, bgK, p_qg, p_kg);

    // 4) gated causal flash attention -> z [B,S,H,DH]
    size_t attn_smem = (size_t)(64 * 65 * 3 + 64 * 64 + 128) * sizeof(float); // 66816 B
    cudaFuncSetAttribute(attn_kernel, cudaFuncAttributeMaxDynamicSharedMemorySize, (int)attn_smem);
    attn_kernel<<<dim3(B_ * H_, S_ / 64), 256, attn_smem>>>(p_q, p_k, p_v, p_qg, p_kg, p_z);

    // 5) output projection: [4096,1536] @ [1536,768] -> out
    sgemm_kernel<false, false><<<dim3(D_ / 64, BS_ / 128), 256>>>(p_z, p_won, nullptr, out, BS_, D_, HD_);
}

// round 6
// speedup vs baseline: 1.7589x; 1.7589x over previous
#include <cuda_runtime.h>
#include <math.h>

#define B_  4
#define S_  1024
#define D_  768
#define H_  24
#define DH_ 64
#define BS_ (B_*S_)    // 4096 tokens
#define HD_ (H_*DH_)   // 1536

// ---------------- scratch (static device globals; no allocation) ----------------
__device__ float g_q[BS_*HD_];
__device__ float g_k[BS_*HD_];
__device__ float g_v[BS_*HD_];
__device__ float g_z[BS_*HD_];
__device__ float g_qg[BS_*H_];
__device__ float g_kg[BS_*H_];
__device__ float g_wvn[H_*D_*DH_];
__device__ float g_won[H_*DH_*D_];
__device__ float g_invv[HD_];
__device__ float g_invo[HD_];

// ---------------- weight normalization ----------------
__global__ void norm_v_kernel(const float* __restrict__ wv, float* __restrict__ invn) {
    int c = blockIdx.x;            // h*64+dh
    int h = c >> 6, dh = c & 63;
    const float* p = wv + (size_t)h * D_ * DH_ + dh;
    float s = 0.f;
    for (int m = threadIdx.x; m < D_; m += 256) { float t = p[(size_t)m * DH_]; s += t * t; }
    __shared__ float red[256];
    red[threadIdx.x] = s; __syncthreads();
    for (int o = 128; o; o >>= 1) { if (threadIdx.x < o) red[threadIdx.x] += red[threadIdx.x + o]; __syncthreads(); }
    if (threadIdx.x == 0) invn[c] = 1.0f / fmaxf(sqrtf(red[0]), 1e-12f);
}
__global__ void norm_o_kernel(const float* __restrict__ wo, float* __restrict__ invn) {
    int r = blockIdx.x;
    const float* p = wo + (size_t)r * D_;
    float s = 0.f;
    for (int m = threadIdx.x; m < D_; m += 256) { float t = p[m]; s += t * t; }
    __shared__ float red[256];
    red[threadIdx.x] = s; __syncthreads();
    for (int o = 128; o; o >>= 1) { if (threadIdx.x < o) red[threadIdx.x] += red[threadIdx.x + o]; __syncthreads(); }
    if (threadIdx.x == 0) invn[r] = 1.0f / fmaxf(sqrtf(red[0]), 1e-12f);
}
__global__ void scale_v_kernel(const float* __restrict__ wv, const float* __restrict__ invn,
                               float* __restrict__ out) {
    int i = blockIdx.x * 256 + threadIdx.x;
    int h = i / (D_ * DH_), dh = i & 63;
    out[i] = wv[i] * invn[h * 64 + dh];
}
__global__ void scale_o_kernel(const float* __restrict__ wo, const float* __restrict__ invn,
                               float* __restrict__ out) {
    int i = blockIdx.x * 256 + threadIdx.x;
    out[i] = wo[i] * invn[i / D_];
}

// ---------------- TF32 helpers ----------------
__device__ __forceinline__ unsigned f2tf(float x) {
    unsigned r; asm("cvt.rna.tf32.f32 %0, %1;" : "=r"(r) : "f"(x)); return r;
}
__device__ __forceinline__ void mma_tf32(float c[4],
                                         unsigned a0, unsigned a1, unsigned a2, unsigned a3,
                                         unsigned b0, unsigned b1) {
    asm volatile("mma.sync.aligned.m16n8k8.row.col.f32.tf32.tf32.f32 "
                 "{%0,%1,%2,%3}, {%4,%5,%6,%7}, {%8,%9}, {%0,%1,%2,%3};"
                 : "+f"(c[0]), "+f"(c[1]), "+f"(c[2]), "+f"(c[3])
                 : "r"(a0), "r"(a1), "r"(a2), "r"(a3), "r"(b0), "r"(b1));
}

// ---------------- TF32 tensor-core GEMM (3xTF32 split, fp32 accuracy) ----------------
// Y[M,N] = A[M,K] @ W (+bias).  BM=128, BN=64, BK=16, 256 threads (8 warps).
// Warp tile 32x32 (2 m16 x 4 n8 mma tiles). A smem [k][m] stride 136, B smem [k][n] stride 72
// => all fragment LDS lanes hit distinct banks (8*tig + gid).
// HEADW: W is [H][K][64] per-head (BN==64==one head). Bias indexed by global column.
template<bool HEADW, bool BIAS>
__global__ void tgemm_kernel(const float* __restrict__ A, const float* __restrict__ W,
                             const float* __restrict__ bias, float* __restrict__ Y,
                             int M, int N, int K)
{
    __shared__ __align__(16) unsigned Ah[16][136];
    __shared__ __align__(16) unsigned Al[16][136];
    __shared__ __align__(16) unsigned Bh[16][72];
    __shared__ __align__(16) unsigned Bl[16][72];

    int tid = threadIdx.x;
    int wid = tid >> 5, lane = tid & 31;
    int gid = lane >> 2, tig = lane & 3;
    int wm = wid & 3, wn = wid >> 2;            // warp tile origin: (32*wm, 32*wn)
    int m0 = blockIdx.y * 128, n0 = blockIdx.x * 64;
    const float* Wb = HEADW ? (W + (size_t)(n0 >> 6) * K * 64) : (W + n0);

    int ai = tid >> 1;             // A row 0..127
    int ak = (tid & 1) * 8;        // k offset 0/8
    int bkk = tid >> 4;            // B k row 0..15
    int bn  = (tid & 15) * 4;      // B col 0..60

    float c[2][4][4];
#pragma unroll
    for (int mi = 0; mi < 2; mi++)
#pragma unroll
        for (int ni = 0; ni < 4; ni++)
#pragma unroll
            for (int j = 0; j < 4; j++) c[mi][ni][j] = 0.f;

    for (int k0 = 0; k0 < K; k0 += 16) {
        // ---- A tile: 128x16 fp32 -> hi/lo tf32, stored [k][m]
        const float* pa = A + (size_t)(m0 + ai) * K + k0 + ak;
        float4 a4_0 = *(const float4*)pa;
        float4 a4_1 = *(const float4*)(pa + 4);
        float av[8] = {a4_0.x, a4_0.y, a4_0.z, a4_0.w, a4_1.x, a4_1.y, a4_1.z, a4_1.w};
#pragma unroll
        for (int j = 0; j < 8; j++) {
            unsigned h = f2tf(av[j]);
            float lo = av[j] - __uint_as_float(h);
            Ah[ak + j][ai] = h;
            Al[ak + j][ai] = f2tf(lo);
        }
        // ---- B tile: 16x64 fp32 -> hi/lo tf32, stored [k][n]
        float4 b4;
        if (HEADW) b4 = *(const float4*)&Wb[(size_t)(k0 + bkk) * 64 + bn];
        else       b4 = *(const float4*)&Wb[(size_t)(k0 + bkk) * N + bn];
        {
            float bv[4] = {b4.x, b4.y, b4.z, b4.w};
            uint4 hb, lb;
            unsigned* hp = (unsigned*)&hb; unsigned* lp = (unsigned*)&lb;
#pragma unroll
            for (int j = 0; j < 4; j++) {
                unsigned h = f2tf(bv[j]);
                hp[j] = h;
                lp[j] = f2tf(bv[j] - __uint_as_float(h));
            }
            *(uint4*)&Bh[bkk][bn] = hb;
            *(uint4*)&Bl[bkk][bn] = lb;
        }
        __syncthreads();

#pragma unroll
        for (int ks = 0; ks < 16; ks += 8) {
            int kr = ks + tig;
            unsigned ah[2][4], al2[2][4], bh[4][2], bl[4][2];
#pragma unroll
            for (int mi = 0; mi < 2; mi++) {
                int m = wm * 32 + mi * 16 + gid;
                ah[mi][0] = Ah[kr][m];     ah[mi][1] = Ah[kr][m + 8];
                ah[mi][2] = Ah[kr + 4][m]; ah[mi][3] = Ah[kr + 4][m + 8];
                al2[mi][0] = Al[kr][m];     al2[mi][1] = Al[kr][m + 8];
                al2[mi][2] = Al[kr + 4][m]; al2[mi][3] = Al[kr + 4][m + 8];
            }
#pragma unroll
            for (int ni = 0; ni < 4; ni++) {
                int n = wn * 32 + ni * 8 + gid;
                bh[ni][0] = Bh[kr][n]; bh[ni][1] = Bh[kr + 4][n];
                bl[ni][0] = Bl[kr][n]; bl[ni][1] = Bl[kr + 4][n];
            }
#pragma unroll
            for (int mi = 0; mi < 2; mi++)
#pragma unroll
                for (int ni = 0; ni < 4; ni++) {
                    mma_tf32(c[mi][ni], ah[mi][0], ah[mi][1], ah[mi][2], ah[mi][3],
                             bh[ni][0], bh[ni][1]);
                    mma_tf32(c[mi][ni], ah[mi][0], ah[mi][1], ah[mi][2], ah[mi][3],
                             bl[ni][0], bl[ni][1]);
                    mma_tf32(c[mi][ni], al2[mi][0], al2[mi][1], al2[mi][2], al2[mi][3],
                             bh[ni][0], bh[ni][1]);
                }
        }
        __syncthreads();
    }

    // ---- epilogue
#pragma unroll
    for (int mi = 0; mi < 2; mi++) {
        int row = m0 + wm * 32 + mi * 16 + gid;
#pragma unroll
        for (int ni = 0; ni < 4; ni++) {
            int col = n0 + wn * 32 + ni * 8 + tig * 2;
            float b0 = 0.f, b1 = 0.f;
            if (BIAS) { b0 = bias[col]; b1 = bias[col + 1]; }
            float2 o0 = make_float2(c[mi][ni][0] + b0, c[mi][ni][1] + b1);
            float2 o1 = make_float2(c[mi][ni][2] + b0, c[mi][ni][3] + b1);
            *(float2*)&Y[(size_t)row * N + col] = o0;
            *(float2*)&Y[(size_t)(row + 8) * N + col] = o1;
        }
    }
}

// ---------------- gate projections (DG=1) ----------------
__global__ void gates_kernel(const float* __restrict__ x,
                             const float* __restrict__ wq, const float* __restrict__ wk,
                             const float* __restrict__ bq, const float* __restrict__ bk,
                             float* __restrict__ qg, float* __restrict__ kg)
{
    __shared__ float xs[D_];
    int t = blockIdx.x;
    const float* xp = x + (size_t)t * D_;
    for (int i = threadIdx.x; i < D_; i += 256) xs[i] = xp[i];
    __syncthreads();
    int w = threadIdx.x >> 5, lane = threadIdx.x & 31;
#pragma unroll
    for (int hh = 0; hh < 3; hh++) {
        int h = w * 3 + hh;
        const float* wqp = wq + (size_t)h * D_;
        const float* wkp = wk + (size_t)h * D_;
        float sq = 0.f, sk = 0.f;
        for (int m = lane; m < D_; m += 32) { float xv = xs[m]; sq += xv * wqp[m]; sk += xv * wkp[m]; }
#pragma unroll
        for (int o = 16; o; o >>= 1) {
            sq += __shfl_xor_sync(0xffffffffu, sq, o);
            sk += __shfl_xor_sync(0xffffffffu, sk, o);
        }
        if (lane == 0) {
            qg[(size_t)t * H_ + h] = sq + bq[h];
            kg[(size_t)t * H_ + h] = sk + bk[h];
        }
    }
}

// ---------------- flash-style gated causal attention ----------------
__global__ void attn_kernel(const float* __restrict__ q, const float* __restrict__ k,
                            const float* __restrict__ v, const float* __restrict__ qg,
                            const float* __restrict__ kg, float* __restrict__ z)
{
    extern __shared__ float sm[];
    float* Qs  = sm;               // [64][65]
    float* Ks  = Qs + 64 * 65;     // [64][65]
    float* Vs  = Ks + 64 * 65;     // [64][64]
    float* Ps  = Vs + 64 * 64;     // [64][65]
    float* qgs = Ps + 64 * 65;     // [64]
    float* kgs = qgs + 64;         // [64]

    int bh = blockIdx.x; int b = bh / H_, h = bh % H_;
    int qt = blockIdx.y;
    int tid = threadIdx.x, ty = tid >> 4, tx = tid & 15;

    const size_t qbase = ((size_t)(b * S_ + qt * 64) * H_ + h) * 64;

#pragma unroll
    for (int it = 0; it < 4; it++) {
        int id = tid * 4 + it * 1024;
        int r = id >> 6, dh = id & 63;
        float4 t4 = *(const float4*)&q[qbase + (size_t)r * HD_ + dh];
        Qs[r * 65 + dh] = t4.x; Qs[r * 65 + dh + 1] = t4.y;
        Qs[r * 65 + dh + 2] = t4.z; Qs[r * 65 + dh + 3] = t4.w;
    }
    if (tid < 64) qgs[tid] = qg[(size_t)(b * S_ + qt * 64 + tid) * H_ + h];

    float m_r[4], l_r[4], acc[4][4];
#pragma unroll
    for (int i = 0; i < 4; i++) {
        m_r[i] = -1e30f; l_r[i] = 0.f;
#pragma unroll
        for (int j = 0; j < 4; j++) acc[i][j] = 0.f;
    }

    for (int kt = 0; kt <= qt; kt++) {
        __syncthreads();
        const size_t kbase = ((size_t)(b * S_ + kt * 64) * H_ + h) * 64;
#pragma unroll
        for (int it = 0; it < 4; it++) {
            int id = tid * 4 + it * 1024;
            int r = id >> 6, dh = id & 63;
            float4 t4 = *(const float4*)&k[kbase + (size_t)r * HD_ + dh];
            Ks[r * 65 + dh] = t4.x; Ks[r * 65 + dh + 1] = t4.y;
            Ks[r * 65 + dh + 2] = t4.z; Ks[r * 65 + dh + 3] = t4.w;
            float4 v4 = *(const float4*)&v[kbase + (size_t)r * HD_ + dh];
            *(float4*)&Vs[r * 64 + dh] = v4;
        }
        if (tid < 64) kgs[tid] = kg[(size_t)(b * S_ + kt * 64 + tid) * H_ + h];
        __syncthreads();

        float s[4][4];
#pragma unroll
        for (int i = 0; i < 4; i++)
#pragma unroll
            for (int j = 0; j < 4; j++) s[i][j] = 0.f;
        for (int dh = 0; dh < 64; dh++) {
            float qv[4], kv[4];
#pragma unroll
            for (int i = 0; i < 4; i++) qv[i] = Qs[(4 * ty + i) * 65 + dh];
#pragma unroll
            for (int j = 0; j < 4; j++) kv[j] = Ks[(4 * tx + j) * 65 + dh];
#pragma unroll
            for (int i = 0; i < 4; i++)
#pragma unroll
                for (int j = 0; j < 4; j++) s[i][j] += qv[i] * kv[j];
        }
#pragma unroll
        for (int i = 0; i < 4; i++)
#pragma unroll
            for (int j = 0; j < 4; j++) s[i][j] *= 0.125f;
        if (kt == qt) {
#pragma unroll
            for (int i = 0; i < 4; i++)
#pragma unroll
                for (int j = 0; j < 4; j++)
                    if (4 * tx + j > 4 * ty + i) s[i][j] = -1e30f;
        }
#pragma unroll
        for (int i = 0; i < 4; i++) {
            float mm = fmaxf(fmaxf(s[i][0], s[i][1]), fmaxf(s[i][2], s[i][3]));
#pragma unroll
            for (int o = 8; o; o >>= 1) mm = fmaxf(mm, __shfl_xor_sync(0xffffffffu, mm, o));
            float mn = fmaxf(m_r[i], mm);
            float alpha = __expf(m_r[i] - mn);
            m_r[i] = mn;
            float p[4], rs = 0.f;
#pragma unroll
            for (int j = 0; j < 4; j++) { p[j] = __expf(s[i][j] - mn); rs += p[j]; }
#pragma unroll
            for (int o = 8; o; o >>= 1) rs += __shfl_xor_sync(0xffffffffu, rs, o);
            l_r[i] = l_r[i] * alpha + rs;
#pragma unroll
            for (int j = 0; j < 4; j++) acc[i][j] *= alpha;
            float gq = qgs[4 * ty + i];
#pragma unroll
            for (int j = 0; j < 4; j++) {
                float g = gq * kgs[4 * tx + j];
                g = fminf(fmaxf(g, 0.f), 1.f);
                Ps[(4 * ty + i) * 65 + 4 * tx + j] = g * p[j];
            }
        }
        __syncthreads();
        for (int kk = 0; kk < 64; kk++) {
            float4 v4 = *(const float4*)&Vs[kk * 64 + 4 * tx];
            float vv[4] = {v4.x, v4.y, v4.z, v4.w};
            float pv[4];
#pragma unroll
            for (int i = 0; i < 4; i++) pv[i] = Ps[(4 * ty + i) * 65 + kk];
#pragma unroll
            for (int i = 0; i < 4; i++)
#pragma unroll
                for (int j = 0; j < 4; j++) acc[i][j] += pv[i] * vv[j];
        }
    }

#pragma unroll
    for (int i = 0; i < 4; i++) {
        float inv = 1.f / l_r[i];
        float4 o;
        o.x = acc[i][0] * inv; o.y = acc[i][1] * inv;
        o.z = acc[i][2] * inv; o.w = acc[i][3] * inv;
        *(float4*)&z[qbase + (size_t)(4 * ty + i) * HD_ + 4 * tx] = o;
    }
}

// ---------------- launch ----------------
extern "C" void kernel_launch(void* const* d_in, const int* in_sizes, int n_in,
                              void* d_out, int out_size) {
    const float* x    = (const float*)d_in[0];
    const float* W_Q  = (const float*)d_in[1];
    const float* W_K  = (const float*)d_in[2];
    const float* W_V  = (const float*)d_in[3];
    const float* W_O  = (const float*)d_in[4];
    const float* b_Q  = (const float*)d_in[5];
    const float* b_K  = (const float*)d_in[6];
    const float* b_V  = (const float*)d_in[7];
    const float* WgQ  = (const float*)d_in[8];
    const float* WgK  = (const float*)d_in[9];
    const float* bgQ  = (const float*)d_in[10];
    const float* bgK  = (const float*)d_in[11];
    float* out = (float*)d_out;

    float *p_q, *p_k, *p_v, *p_z, *p_qg, *p_kg, *p_wvn, *p_won, *p_invv, *p_invo;
    cudaGetSymbolAddress((void**)&p_q,    g_q);
    cudaGetSymbolAddress((void**)&p_k,    g_k);
    cudaGetSymbolAddress((void**)&p_v,    g_v);
    cudaGetSymbolAddress((void**)&p_z,    g_z);
    cudaGetSymbolAddress((void**)&p_qg,   g_qg);
    cudaGetSymbolAddress((void**)&p_kg,   g_kg);
    cudaGetSymbolAddress((void**)&p_wvn,  g_wvn);
    cudaGetSymbolAddress((void**)&p_won,  g_won);
    cudaGetSymbolAddress((void**)&p_invv, g_invv);
    cudaGetSymbolAddress((void**)&p_invo, g_invo);

    // 1) weight norms + rescale
    norm_v_kernel<<<HD_, 256>>>(W_V, p_invv);
    norm_o_kernel<<<HD_, 256>>>(W_O, p_invo);
    scale_v_kernel<<<(H_*D_*DH_) / 256, 256>>>(W_V, p_invv, p_wvn);
    scale_o_kernel<<<(H_*DH_*D_) / 256, 256>>>(W_O, p_invo, p_won);

    // 2) Q/K/V projections on tensor cores (3xTF32)
    dim3 pg(HD_ / 64, BS_ / 128);
    tgemm_kernel<true, true><<<pg, 256>>>(x, W_Q,   b_Q, p_q, BS_, HD_, D_);
    tgemm_kernel<true, true><<<pg, 256>>>(x, W_K,   b_K, p_k, BS_, HD_, D_);
    tgemm_kernel<true, true><<<pg, 256>>>(x, p_wvn, b_V, p_v, BS_, HD_, D_);

    // 3) gate projections
    gates_kernel<<<BS_, 256>>>(x, WgQ, WgK, bgQ, bgK, p_qg, p_kg);

    // 4) gated causal flash attention -> z [B,S,H,DH]
    size_t attn_smem = (size_t)(64 * 65 * 3 + 64 * 64 + 128) * sizeof(float);
    cudaFuncSetAttribute(attn_kernel, cudaFuncAttributeMaxDynamicSharedMemorySize, (int)attn_smem);
    attn_kernel<<<dim3(B_ * H_, S_ / 64), 256, attn_smem>>>(p_q, p_k, p_v, p_qg, p_kg, p_z);

    // 5) output projection on tensor cores
    tgemm_kernel<false, false><<<dim3(D_ / 64, BS_ / 128), 256>>>(p_z, p_won, nullptr, out, BS_, D_, HD_);
}

// round 7
// speedup vs baseline: 2.2658x; 1.2882x over previous
#include <cuda_runtime.h>
#include <cuda_fp16.h>
#include <math.h>

#define B_  4
#define S_  1024
#define D_  768
#define H_  24
#define DH_ 64
#define BS_ (B_*S_)    // 4096 tokens
#define HD_ (H_*DH_)   // 1536

// ---------------- scratch (static device globals; no allocation) ----------------
__device__ float g_q[BS_*HD_];
__device__ float g_k[BS_*HD_];
__device__ float g_v[BS_*HD_];
__device__ float g_vt[BS_*HD_];   // V transposed: [b][h][dh][s]
__device__ float g_z[BS_*HD_];
__device__ float g_qg[BS_*H_];
__device__ float g_kg[BS_*H_];
__device__ float g_wvn[H_*D_*DH_];
__device__ float g_won[H_*DH_*D_];
__device__ float g_invv[HD_];
__device__ float g_invo[HD_];

// ---------------- weight normalization ----------------
__global__ void norm_v_kernel(const float* __restrict__ wv, float* __restrict__ invn) {
    int c = blockIdx.x;            // h*64+dh
    int h = c >> 6, dh = c & 63;
    const float* p = wv + (size_t)h * D_ * DH_ + dh;
    float s = 0.f;
    for (int m = threadIdx.x; m < D_; m += 256) { float t = p[(size_t)m * DH_]; s += t * t; }
    __shared__ float red[256];
    red[threadIdx.x] = s; __syncthreads();
    for (int o = 128; o; o >>= 1) { if (threadIdx.x < o) red[threadIdx.x] += red[threadIdx.x + o]; __syncthreads(); }
    if (threadIdx.x == 0) invn[c] = 1.0f / fmaxf(sqrtf(red[0]), 1e-12f);
}
__global__ void norm_o_kernel(const float* __restrict__ wo, float* __restrict__ invn) {
    int r = blockIdx.x;
    const float* p = wo + (size_t)r * D_;
    float s = 0.f;
    for (int m = threadIdx.x; m < D_; m += 256) { float t = p[m]; s += t * t; }
    __shared__ float red[256];
    red[threadIdx.x] = s; __syncthreads();
    for (int o = 128; o; o >>= 1) { if (threadIdx.x < o) red[threadIdx.x] += red[threadIdx.x + o]; __syncthreads(); }
    if (threadIdx.x == 0) invn[r] = 1.0f / fmaxf(sqrtf(red[0]), 1e-12f);
}
__global__ void scale_v_kernel(const float* __restrict__ wv, const float* __restrict__ invn,
                               float* __restrict__ out) {
    int i = blockIdx.x * 256 + threadIdx.x;
    int h = i / (D_ * DH_), dh = i & 63;
    out[i] = wv[i] * invn[h * 64 + dh];
}
__global__ void scale_o_kernel(const float* __restrict__ wo, const float* __restrict__ invn,
                               float* __restrict__ out) {
    int i = blockIdx.x * 256 + threadIdx.x;
    out[i] = wo[i] * invn[i / D_];
}

// ---------------- TF32 helpers ----------------
__device__ __forceinline__ unsigned f2tf(float x) {
    unsigned r; asm("cvt.rna.tf32.f32 %0, %1;" : "=r"(r) : "f"(x)); return r;
}
__device__ __forceinline__ void mma_tf32(float c[4],
                                         unsigned a0, unsigned a1, unsigned a2, unsigned a3,
                                         unsigned b0, unsigned b1) {
    asm volatile("mma.sync.aligned.m16n8k8.row.col.f32.tf32.tf32.f32 "
                 "{%0,%1,%2,%3}, {%4,%5,%6,%7}, {%8,%9}, {%0,%1,%2,%3};"
                 : "+f"(c[0]), "+f"(c[1]), "+f"(c[2]), "+f"(c[3])
                 : "r"(a0), "r"(a1), "r"(a2), "r"(a3), "r"(b0), "r"(b1));
}
__device__ __forceinline__ void mma_f16(float c[4],
                                        unsigned a0, unsigned a1, unsigned a2, unsigned a3,
                                        unsigned b0, unsigned b1) {
    asm volatile("mma.sync.aligned.m16n8k16.row.col.f32.f16.f16.f32 "
                 "{%0,%1,%2,%3}, {%4,%5,%6,%7}, {%8,%9}, {%0,%1,%2,%3};"
                 : "+f"(c[0]), "+f"(c[1]), "+f"(c[2]), "+f"(c[3])
                 : "r"(a0), "r"(a1), "r"(a2), "r"(a3), "r"(b0), "r"(b1));
}
__device__ __forceinline__ unsigned packh2(float x, float y) {
    __half2 h = __floats2half2_rn(x, y);
    return *(unsigned*)&h;
}

// ---------------- TF32 tensor-core GEMM (3xTF32 split, fp32 accuracy) ----------------
template<bool HEADW, bool BIAS>
__global__ void tgemm_kernel(const float* __restrict__ A, const float* __restrict__ W,
                             const float* __restrict__ bias, float* __restrict__ Y,
                             int M, int N, int K)
{
    __shared__ __align__(16) unsigned Ah[16][136];
    __shared__ __align__(16) unsigned Al[16][136];
    __shared__ __align__(16) unsigned Bh[16][72];
    __shared__ __align__(16) unsigned Bl[16][72];

    int tid = threadIdx.x;
    int wid = tid >> 5, lane = tid & 31;
    int gid = lane >> 2, tig = lane & 3;
    int wm = wid & 3, wn = wid >> 2;
    int m0 = blockIdx.y * 128, n0 = blockIdx.x * 64;
    const float* Wb = HEADW ? (W + (size_t)(n0 >> 6) * K * 64) : (W + n0);

    int ai = tid >> 1;
    int ak = (tid & 1) * 8;
    int bkk = tid >> 4;
    int bn  = (tid & 15) * 4;

    float c[2][4][4];
#pragma unroll
    for (int mi = 0; mi < 2; mi++)
#pragma unroll
        for (int ni = 0; ni < 4; ni++)
#pragma unroll
            for (int j = 0; j < 4; j++) c[mi][ni][j] = 0.f;

    for (int k0 = 0; k0 < K; k0 += 16) {
        const float* pa = A + (size_t)(m0 + ai) * K + k0 + ak;
        float4 a4_0 = *(const float4*)pa;
        float4 a4_1 = *(const float4*)(pa + 4);
        float av[8] = {a4_0.x, a4_0.y, a4_0.z, a4_0.w, a4_1.x, a4_1.y, a4_1.z, a4_1.w};
#pragma unroll
        for (int j = 0; j < 8; j++) {
            unsigned h = f2tf(av[j]);
            float lo = av[j] - __uint_as_float(h);
            Ah[ak + j][ai] = h;
            Al[ak + j][ai] = f2tf(lo);
        }
        float4 b4;
        if (HEADW) b4 = *(const float4*)&Wb[(size_t)(k0 + bkk) * 64 + bn];
        else       b4 = *(const float4*)&Wb[(size_t)(k0 + bkk) * N + bn];
        {
            float bv[4] = {b4.x, b4.y, b4.z, b4.w};
            uint4 hb, lb;
            unsigned* hp = (unsigned*)&hb; unsigned* lp = (unsigned*)&lb;
#pragma unroll
            for (int j = 0; j < 4; j++) {
                unsigned h = f2tf(bv[j]);
                hp[j] = h;
                lp[j] = f2tf(bv[j] - __uint_as_float(h));
            }
            *(uint4*)&Bh[bkk][bn] = hb;
            *(uint4*)&Bl[bkk][bn] = lb;
        }
        __syncthreads();

#pragma unroll
        for (int ks = 0; ks < 16; ks += 8) {
            int kr = ks + tig;
            unsigned ah[2][4], al2[2][4], bh[4][2], bl[4][2];
#pragma unroll
            for (int mi = 0; mi < 2; mi++) {
                int m = wm * 32 + mi * 16 + gid;
                ah[mi][0] = Ah[kr][m];     ah[mi][1] = Ah[kr][m + 8];
                ah[mi][2] = Ah[kr + 4][m]; ah[mi][3] = Ah[kr + 4][m + 8];
                al2[mi][0] = Al[kr][m];     al2[mi][1] = Al[kr][m + 8];
                al2[mi][2] = Al[kr + 4][m]; al2[mi][3] = Al[kr + 4][m + 8];
            }
#pragma unroll
            for (int ni = 0; ni < 4; ni++) {
                int n = wn * 32 + ni * 8 + gid;
                bh[ni][0] = Bh[kr][n]; bh[ni][1] = Bh[kr + 4][n];
                bl[ni][0] = Bl[kr][n]; bl[ni][1] = Bl[kr + 4][n];
            }
#pragma unroll
            for (int mi = 0; mi < 2; mi++)
#pragma unroll
                for (int ni = 0; ni < 4; ni++) {
                    mma_tf32(c[mi][ni], ah[mi][0], ah[mi][1], ah[mi][2], ah[mi][3],
                             bh[ni][0], bh[ni][1]);
                    mma_tf32(c[mi][ni], ah[mi][0], ah[mi][1], ah[mi][2], ah[mi][3],
                             bl[ni][0], bl[ni][1]);
                    mma_tf32(c[mi][ni], al2[mi][0], al2[mi][1], al2[mi][2], al2[mi][3],
                             bh[ni][0], bh[ni][1]);
                }
        }
        __syncthreads();
    }

#pragma unroll
    for (int mi = 0; mi < 2; mi++) {
        int row = m0 + wm * 32 + mi * 16 + gid;
#pragma unroll
        for (int ni = 0; ni < 4; ni++) {
            int col = n0 + wn * 32 + ni * 8 + tig * 2;
            float b0 = 0.f, b1 = 0.f;
            if (BIAS) { b0 = bias[col]; b1 = bias[col + 1]; }
            float2 o0 = make_float2(c[mi][ni][0] + b0, c[mi][ni][1] + b1);
            float2 o1 = make_float2(c[mi][ni][2] + b0, c[mi][ni][3] + b1);
            *(float2*)&Y[(size_t)row * N + col] = o0;
            *(float2*)&Y[(size_t)(row + 8) * N + col] = o1;
        }
    }
}

// ---------------- gate projections (DG=1) ----------------
__global__ void gates_kernel(const float* __restrict__ x,
                             const float* __restrict__ wq, const float* __restrict__ wk,
                             const float* __restrict__ bq, const float* __restrict__ bk,
                             float* __restrict__ qg, float* __restrict__ kg)
{
    __shared__ float xs[D_];
    int t = blockIdx.x;
    const float* xp = x + (size_t)t * D_;
    for (int i = threadIdx.x; i < D_; i += 256) xs[i] = xp[i];
    __syncthreads();
    int w = threadIdx.x >> 5, lane = threadIdx.x & 31;
#pragma unroll
    for (int hh = 0; hh < 3; hh++) {
        int h = w * 3 + hh;
        const float* wqp = wq + (size_t)h * D_;
        const float* wkp = wk + (size_t)h * D_;
        float sq = 0.f, sk = 0.f;
        for (int m = lane; m < D_; m += 32) { float xv = xs[m]; sq += xv * wqp[m]; sk += xv * wkp[m]; }
#pragma unroll
        for (int o = 16; o; o >>= 1) {
            sq += __shfl_xor_sync(0xffffffffu, sq, o);
            sk += __shfl_xor_sync(0xffffffffu, sk, o);
        }
        if (lane == 0) {
            qg[(size_t)t * H_ + h] = sq + bq[h];
            kg[(size_t)t * H_ + h] = sk + bk[h];
        }
    }
}

// ---------------- V transpose: [token][h][dh] -> [b][h][dh][s] ----------------
__global__ void transpose_v_kernel(const float* __restrict__ v, float* __restrict__ vt) {
    __shared__ float ts[64][65];
    int blk = blockIdx.x;
    int st = blk & 15;
    int h  = (blk >> 4) % H_;
    int b  = blk / (16 * H_);
    size_t rbase = ((size_t)(b * S_ + st * 64)) * HD_ + h * 64;
#pragma unroll
    for (int it = 0; it < 4; it++) {
        int idx = threadIdx.x + it * 256;          // 1024 float4 slots
        int r = idx >> 4, c4 = (idx & 15) * 4;
        float4 f = *(const float4*)&v[rbase + (size_t)r * HD_ + c4];
        ts[r][c4] = f.x; ts[r][c4 + 1] = f.y; ts[r][c4 + 2] = f.z; ts[r][c4 + 3] = f.w;
    }
    __syncthreads();
    size_t wbase = ((size_t)((b * H_ + h) * 64)) * S_ + st * 64;
#pragma unroll
    for (int it = 0; it < 4; it++) {
        int idx = threadIdx.x + it * 256;
        int c = idx >> 4, r4 = (idx & 15) * 4;
        float4 o;
        o.x = ts[r4][c]; o.y = ts[r4 + 1][c]; o.z = ts[r4 + 2][c]; o.w = ts[r4 + 3][c];
        *(float4*)&vt[wbase + (size_t)c * S_ + r4] = o;
    }
}

// ---------------- flash attention on tensor cores (fp16 hi/lo QK, fp16 PV) ----------------
// block = 128 threads (4 warps); warp w owns q-rows 16w..16w+15 of a 64-row q-tile.
// grid: (B*H, S/64).
#define KST 36   // u32 stride: bank = 4*gid + tig -> conflict-free fragment loads
__global__ __launch_bounds__(128) void attn_mma_kernel(
    const float* __restrict__ q, const float* __restrict__ k,
    const float* __restrict__ vt, const float* __restrict__ qg,
    const float* __restrict__ kg, float* __restrict__ z)
{
    __shared__ unsigned Khi[64 * KST];
    __shared__ unsigned Klo[64 * KST];
    __shared__ unsigned Vts[64 * KST];
    __shared__ float kgs[64];

    int bh = blockIdx.x, b = bh / H_, h = bh % H_;
    int qt = blockIdx.y;
    int tid = threadIdx.x;
    int w = tid >> 5, lane = tid & 31;
    int gid = lane >> 2, tig = lane & 3;

    // ---- Q fragments (register-resident, scaled by 1/sqrt(DH)) ----
    int row0 = qt * 64 + w * 16 + gid;                       // global seq row (gid half)
    size_t qr0 = ((size_t)(b * S_) + row0) * HD_ + h * 64;
    size_t qr1 = qr0 + 8 * (size_t)HD_;
    unsigned qh[4][4], ql[4][4];
#pragma unroll
    for (int ks = 0; ks < 4; ks++) {
        int c0 = 2 * tig + 16 * ks;
        float2 f[4];
        f[0] = *(const float2*)&q[qr0 + c0];
        f[1] = *(const float2*)&q[qr1 + c0];
        f[2] = *(const float2*)&q[qr0 + c0 + 8];
        f[3] = *(const float2*)&q[qr1 + c0 + 8];
#pragma unroll
        for (int j = 0; j < 4; j++) {
            float x0 = f[j].x * 0.125f, x1 = f[j].y * 0.125f;
            __half h0 = __float2half_rn(x0), h1 = __float2half_rn(x1);
            float l0 = x0 - __half2float(h0), l1 = x1 - __half2float(h1);
            __half2 hp = __halves2half2(h0, h1);
            qh[ks][j] = *(unsigned*)&hp;
            ql[ks][j] = packh2(l0, l1);
        }
    }
    float qg0 = qg[(size_t)(b * S_ + row0) * H_ + h];
    float qg1 = qg[(size_t)(b * S_ + row0 + 8) * H_ + h];

    float acc[8][4];
#pragma unroll
    for (int n = 0; n < 8; n++)
#pragma unroll
        for (int j = 0; j < 4; j++) acc[n][j] = 0.f;
    float m0 = -1e30f, m1 = -1e30f, l0 = 0.f, l1 = 0.f;

    for (int kt = 0; kt <= qt; kt++) {
        __syncthreads();
        // ---- fill K (hi/lo fp16 pairs over dh) ----
        size_t kb = ((size_t)(b * S_ + kt * 64)) * HD_ + h * 64;
#pragma unroll
        for (int it = 0; it < 8; it++) {
            int idx = (tid + it * 128);
            int kp = idx >> 4, dh = (idx & 15) * 4;
            float4 f = *(const float4*)&k[kb + (size_t)kp * HD_ + dh];
            float fv[4] = {f.x, f.y, f.z, f.w};
            __half hv[4]; float lv[4];
#pragma unroll
            for (int j = 0; j < 4; j++) { hv[j] = __float2half_rn(fv[j]); lv[j] = fv[j] - __half2float(hv[j]); }
            __half2 p0 = __halves2half2(hv[0], hv[1]);
            __half2 p1 = __halves2half2(hv[2], hv[3]);
            Khi[kp * KST + (dh >> 1)]     = *(unsigned*)&p0;
            Khi[kp * KST + (dh >> 1) + 1] = *(unsigned*)&p1;
            Klo[kp * KST + (dh >> 1)]     = packh2(lv[0], lv[1]);
            Klo[kp * KST + (dh >> 1) + 1] = packh2(lv[2], lv[3]);
        }
        // ---- fill V (fp16 pairs over kpos; vt layout [b][h][dh][s]) ----
        size_t vb = ((size_t)((b * H_ + h) * 64)) * S_ + kt * 64;
#pragma unroll
        for (int it = 0; it < 16; it++) {
            int u = tid + it * 128;
            int kp = u & 31, dh = u >> 5;
            float2 f = *(const float2*)&vt[vb + (size_t)dh * S_ + 2 * kp];
            Vts[dh * KST + kp] = packh2(f.x, f.y);
        }
        if (tid < 64) kgs[tid] = kg[(size_t)(b * S_ + kt * 64 + tid) * H_ + h];
        __syncthreads();

        int diag = (kt == qt);
        int nfmax = diag ? (2 * w + 2) : 8;
        int ksmax = diag ? (w + 1) : 4;

        // ---- S = Q @ K^T (3-pass fp16 hi/lo) ----
        float c[8][4];
#pragma unroll
        for (int nf = 0; nf < 8; nf++) {
            c[nf][0] = 0.f; c[nf][1] = 0.f; c[nf][2] = 0.f; c[nf][3] = 0.f;
            if (nf < nfmax) {
#pragma unroll
                for (int ks = 0; ks < 4; ks++) {
                    int kb2 = (nf * 8 + gid) * KST + tig + ks * 8;
                    unsigned b0h = Khi[kb2], b1h = Khi[kb2 + 4];
                    unsigned b0l = Klo[kb2], b1l = Klo[kb2 + 4];
                    mma_f16(c[nf], qh[ks][0], qh[ks][1], qh[ks][2], qh[ks][3], b0h, b1h);
                    mma_f16(c[nf], qh[ks][0], qh[ks][1], qh[ks][2], qh[ks][3], b0l, b1l);
                    mma_f16(c[nf], ql[ks][0], ql[ks][1], ql[ks][2], ql[ks][3], b0h, b1h);
                }
            }
        }
        // ---- causal mask on diagonal tile ----
        if (diag) {
            int r0 = w * 16 + gid, r1 = r0 + 8;
#pragma unroll
            for (int nf = 0; nf < 8; nf++) {
                if (nf < nfmax) {
                    int cb = nf * 8 + 2 * tig;
                    if (cb     > r0) c[nf][0] = -1e30f;
                    if (cb + 1 > r0) c[nf][1] = -1e30f;
                    if (cb     > r1) c[nf][2] = -1e30f;
                    if (cb + 1 > r1) c[nf][3] = -1e30f;
                }
            }
        }
        // ---- online softmax + gate, pack P to fp16 A-fragments ----
        float mx0 = -1e30f, mx1 = -1e30f;
#pragma unroll
        for (int nf = 0; nf < 8; nf++) {
            if (nf < nfmax) {
                mx0 = fmaxf(mx0, fmaxf(c[nf][0], c[nf][1]));
                mx1 = fmaxf(mx1, fmaxf(c[nf][2], c[nf][3]));
            }
        }
        mx0 = fmaxf(mx0, __shfl_xor_sync(0xffffffffu, mx0, 1));
        mx0 = fmaxf(mx0, __shfl_xor_sync(0xffffffffu, mx0, 2));
        mx1 = fmaxf(mx1, __shfl_xor_sync(0xffffffffu, mx1, 1));
        mx1 = fmaxf(mx1, __shfl_xor_sync(0xffffffffu, mx1, 2));
        float mn0 = fmaxf(m0, mx0), mn1 = fmaxf(m1, mx1);
        float al0 = __expf(m0 - mn0), al1 = __expf(m1 - mn1);
        m0 = mn0; m1 = mn1;

        unsigned pa[4][4];
        float rs0 = 0.f, rs1 = 0.f;
#pragma unroll
        for (int nf = 0; nf < 8; nf++) {
            if (nf < nfmax) {
                float p0 = __expf(c[nf][0] - mn0);
                float p1 = __expf(c[nf][1] - mn0);
                float p2 = __expf(c[nf][2] - mn1);
                float p3 = __expf(c[nf][3] - mn1);
                rs0 += p0 + p1; rs1 += p2 + p3;
                int cb = nf * 8 + 2 * tig;
                float k0v = kgs[cb], k1v = kgs[cb + 1];
                float g00 = fminf(fmaxf(qg0 * k0v, 0.f), 1.f);
                float g01 = fminf(fmaxf(qg0 * k1v, 0.f), 1.f);
                float g10 = fminf(fmaxf(qg1 * k0v, 0.f), 1.f);
                float g11 = fminf(fmaxf(qg1 * k1v, 0.f), 1.f);
                int ks = nf >> 1, half = (nf & 1) * 2;
                pa[ks][half]     = packh2(g00 * p0, g01 * p1);
                pa[ks][half + 1] = packh2(g10 * p2, g11 * p3);
            }
        }
        rs0 += __shfl_xor_sync(0xffffffffu, rs0, 1);
        rs0 += __shfl_xor_sync(0xffffffffu, rs0, 2);
        rs1 += __shfl_xor_sync(0xffffffffu, rs1, 1);
        rs1 += __shfl_xor_sync(0xffffffffu, rs1, 2);
        l0 = l0 * al0 + rs0;
        l1 = l1 * al1 + rs1;
#pragma unroll
        for (int n = 0; n < 8; n++) {
            acc[n][0] *= al0; acc[n][1] *= al0;
            acc[n][2] *= al1; acc[n][3] *= al1;
        }
        // ---- O += P_gated @ V ----
#pragma unroll
        for (int ks = 0; ks < 4; ks++) {
            if (ks < ksmax) {
#pragma unroll
                for (int nf2 = 0; nf2 < 8; nf2++) {
                    int vb2 = (nf2 * 8 + gid) * KST + tig + ks * 8;
                    mma_f16(acc[nf2], pa[ks][0], pa[ks][1], pa[ks][2], pa[ks][3],
                            Vts[vb2], Vts[vb2 + 4]);
                }
            }
        }
    }

    // ---- epilogue ----
    float i0 = 1.f / l0, i1 = 1.f / l1;
#pragma unroll
    for (int nf2 = 0; nf2 < 8; nf2++) {
        int col = nf2 * 8 + 2 * tig;
        float2 o0 = make_float2(acc[nf2][0] * i0, acc[nf2][1] * i0);
        float2 o1 = make_float2(acc[nf2][2] * i1, acc[nf2][3] * i1);
        *(float2*)&z[qr0 + col] = o0;
        *(float2*)&z[qr1 + col] = o1;
    }
}

// ---------------- launch ----------------
extern "C" void kernel_launch(void* const* d_in, const int* in_sizes, int n_in,
                              void* d_out, int out_size) {
    const float* x    = (const float*)d_in[0];
    const float* W_Q  = (const float*)d_in[1];
    const float* W_K  = (const float*)d_in[2];
    const float* W_V  = (const float*)d_in[3];
    const float* W_O  = (const float*)d_in[4];
    const float* b_Q  = (const float*)d_in[5];
    const float* b_K  = (const float*)d_in[6];
    const float* b_V  = (const float*)d_in[7];
    const float* WgQ  = (const float*)d_in[8];
    const float* WgK  = (const float*)d_in[9];
    const float* bgQ  = (const float*)d_in[10];
    const float* bgK  = (const float*)d_in[11];
    float* out = (float*)d_out;

    float *p_q, *p_k, *p_v, *p_vt, *p_z, *p_qg, *p_kg, *p_wvn, *p_won, *p_invv, *p_invo;
    cudaGetSymbolAddress((void**)&p_q,    g_q);
    cudaGetSymbolAddress((void**)&p_k,    g_k);
    cudaGetSymbolAddress((void**)&p_v,    g_v);
    cudaGetSymbolAddress((void**)&p_vt,   g_vt);
    cudaGetSymbolAddress((void**)&p_z,    g_z);
    cudaGetSymbolAddress((void**)&p_qg,   g_qg);
    cudaGetSymbolAddress((void**)&p_kg,   g_kg);
    cudaGetSymbolAddress((void**)&p_wvn,  g_wvn);
    cudaGetSymbolAddress((void**)&p_won,  g_won);
    cudaGetSymbolAddress((void**)&p_invv, g_invv);
    cudaGetSymbolAddress((void**)&p_invo, g_invo);

    // 1) weight norms + rescale
    norm_v_kernel<<<HD_, 256>>>(W_V, p_invv);
    norm_o_kernel<<<HD_, 256>>>(W_O, p_invo);
    scale_v_kernel<<<(H_*D_*DH_) / 256, 256>>>(W_V, p_invv, p_wvn);
    scale_o_kernel<<<(H_*DH_*D_) / 256, 256>>>(W_O, p_invo, p_won);

    // 2) Q/K/V projections on tensor cores (3xTF32)
    dim3 pg(HD_ / 64, BS_ / 128);
    tgemm_kernel<true, true><<<pg, 256>>>(x, W_Q,   b_Q, p_q, BS_, HD_, D_);
    tgemm_kernel<true, true><<<pg, 256>>>(x, W_K,   b_K, p_k, BS_, HD_, D_);
    tgemm_kernel<true, true><<<pg, 256>>>(x, p_wvn, b_V, p_v, BS_, HD_, D_);

    // 3) gate projections
    gates_kernel<<<BS_, 256>>>(x, WgQ, WgK, bgQ, bgK, p_qg, p_kg);

    // 4) V transpose + tensor-core flash attention -> z [B,S,H,DH]
    transpose_v_kernel<<<B_ * H_ * 16, 256>>>(p_v, p_vt);
    attn_mma_kernel<<<dim3(B_ * H_, S_ / 64), 128>>>(p_q, p_k, p_vt, p_qg, p_kg, p_z);

    // 5) output projection on tensor cores
    tgemm_kernel<false, false><<<dim3(D_ / 64, BS_ / 128), 256>>>(p_z, p_won, nullptr, out, BS_, D_, HD_);
}